// round 1
// baseline (speedup 1.0000x reference)
#include <cuda_runtime.h>
#include <cstdint>

#define S_   4
#define B_   256
#define Q_   1024
#define P_   32768
#define D_   256
#define CH   128          // p per chunk
#define NCH  256          // P_/CH
#define NB   11           // K+1
#define KOUT 10
#define NEG_INF (-1e30f)

// ---- static device scratch (no allocs allowed) ----
__device__ float g_qvec[Q_ * D_];                         // 1 MB
__device__ float g_cand_sc[(size_t)S_ * Q_ * NCH * NB];   // ~46 MB
__device__ int   g_cand_ix[(size_t)S_ * Q_ * NCH * NB];   // ~46 MB
__device__ float g_best_sc[S_ * Q_ * NB];
__device__ int   g_best_ix[S_ * Q_ * NB];

// ============================================================
// Kernel 1: qvec[q,d] = E[s, head[s,b], d] * R[rel[s,b], d]
// ============================================================
__global__ void qvec_kernel(const int* __restrict__ relation,
                            const int* __restrict__ head,
                            const float* __restrict__ ent,
                            const float* __restrict__ rel) {
    int q = blockIdx.x;
    int d = threadIdx.x;
    int s = q >> 8;              // q = s*B + b
    int hd = head[q];
    int rr = relation[q];
    g_qvec[q * D_ + d] = ent[((size_t)s * P_ + hd) * D_ + d] * rel[(size_t)rr * D_ + d];
}

// ============================================================
// Kernel 2: scores + per-(s',q,chunk) exact top-11
// grid: (NCH, S_), block: 256
// smem: E[128][260] + Qv[32][260] + Sc[32][132] + scratch
// ============================================================
#define ESTR 260
#define SSTR 132
#define SMEM_FLOATS (128*ESTR + 32*ESTR + 32*SSTR + 32*8*NB)   // f32 part
#define SMEM_BYTES  ((SMEM_FLOATS + 32*8*NB) * 4)              // + int part

__global__ __launch_bounds__(256) void score_kernel(const float* __restrict__ ent) {
    extern __shared__ float sm[];
    float* sE     = sm;                      // [128][ESTR]
    float* sQv    = sE + 128 * ESTR;         // [32][ESTR]
    float* sS     = sQv + 32 * ESTR;         // [32][SSTR]
    float* scr_sc = sS + 32 * SSTR;          // [32][8][NB]
    int*   scr_ix = (int*)(scr_sc + 32 * 8 * NB);

    const int chunk = blockIdx.x;
    const int sp    = blockIdx.y;
    const int tid   = threadIdx.x;

    // --- stage E chunk: 128 rows x 256 f32, padded rows ---
    const float* Eb = ent + ((size_t)sp * P_ + (size_t)chunk * CH) * D_;
    for (int i = tid; i < CH * (D_ / 4); i += 256) {
        int row = i >> 6, c = i & 63;
        float4 v = ((const float4*)(Eb + (size_t)row * D_))[c];
        *(float4*)(sE + row * ESTR + c * 4) = v;
    }

    const int qg = tid >> 4;   // 0..15  (2 q rows each)
    const int pg = tid & 15;   // 0..15  (8 p cols each, interleaved)
    const int tq = tid >> 3;   // 0..31  (scan phase: q row)
    const int ts = tid & 7;    // 0..7   (scan phase: p segment)

    for (int wave = 0; wave < 32; wave++) {
        __syncthreads();
        // --- stage 32 qvec rows ---
        const float* Qb = g_qvec + (size_t)(wave * 32) * D_;
        for (int i = tid; i < 32 * (D_ / 4); i += 256) {
            int row = i >> 6, c = i & 63;
            float4 v = ((const float4*)(Qb + row * D_))[c];
            *(float4*)(sQv + row * ESTR + c * 4) = v;
        }
        __syncthreads();

        // --- compute 2q x 8p tile per thread ---
        float acc0[8], acc1[8];
        #pragma unroll
        for (int j = 0; j < 8; j++) { acc0[j] = 0.f; acc1[j] = 0.f; }

        for (int d0 = 0; d0 < D_; d0 += 4) {
            float4 a0 = *(const float4*)(sQv + (2 * qg)     * ESTR + d0);
            float4 a1 = *(const float4*)(sQv + (2 * qg + 1) * ESTR + d0);
            #pragma unroll
            for (int j = 0; j < 8; j++) {
                float4 e = *(const float4*)(sE + (pg + 16 * j) * ESTR + d0);
                acc0[j] = fmaf(a0.x, e.x, fmaf(a0.y, e.y, fmaf(a0.z, e.z, fmaf(a0.w, e.w, acc0[j]))));
                acc1[j] = fmaf(a1.x, e.x, fmaf(a1.y, e.y, fmaf(a1.z, e.z, fmaf(a1.w, e.w, acc1[j]))));
            }
        }
        #pragma unroll
        for (int j = 0; j < 8; j++) {
            sS[(2 * qg)     * SSTR + pg + 16 * j] = acc0[j];
            sS[(2 * qg + 1) * SSTR + pg + 16 * j] = acc1[j];
        }
        __syncthreads();

        // --- per-thread top-11 over its 16 p's (exact) ---
        float bs[NB]; int bi[NB];
        #pragma unroll
        for (int r = 0; r < NB; r++) { bs[r] = NEG_INF; bi[r] = 0; }
        for (int i = 0; i < 16; i++) {
            int p = ts * 16 + i;
            float v = sS[tq * SSTR + p];
            if (v > bs[NB - 1]) {
                float cv = v; int ci = chunk * CH + p;
                #pragma unroll
                for (int r = 0; r < NB; r++) {
                    if (cv > bs[r]) {
                        float t0 = bs[r]; int t1 = bi[r];
                        bs[r] = cv; bi[r] = ci; cv = t0; ci = t1;
                    }
                }
            }
        }
        #pragma unroll
        for (int r = 0; r < NB; r++) {
            scr_sc[(tq * 8 + ts) * NB + r] = bs[r];
            scr_ix[(tq * 8 + ts) * NB + r] = bi[r];
        }
        __syncthreads();

        // --- leader merges 8 sorted lists -> chunk top-11 for its q ---
        if (ts == 0) {
            int q = wave * 32 + tq;
            int hd0 = 0, hd1 = 0, hd2 = 0, hd3 = 0, hd4 = 0, hd5 = 0, hd6 = 0, hd7 = 0;
            size_t ob = (((size_t)sp * Q_ + q) * NCH + chunk) * NB;
            for (int r = 0; r < NB; r++) {
                float best = NEG_INF; int bl = 0, bh = 0;
                #define TRY(l, h) { float v = (h < NB) ? scr_sc[(tq*8+(l))*NB + (h)] : NEG_INF; \
                                    if (v > best) { best = v; bl = (l); bh = (h); } }
                TRY(0, hd0) TRY(1, hd1) TRY(2, hd2) TRY(3, hd3)
                TRY(4, hd4) TRY(5, hd5) TRY(6, hd6) TRY(7, hd7)
                #undef TRY
                g_cand_sc[ob + r] = best;
                g_cand_ix[ob + r] = scr_ix[(tq * 8 + bl) * NB + bh];
                if      (bl == 0) hd0++; else if (bl == 1) hd1++;
                else if (bl == 2) hd2++; else if (bl == 3) hd3++;
                else if (bl == 4) hd4++; else if (bl == 5) hd5++;
                else if (bl == 6) hd6++; else               hd7++;
            }
        }
    }
}

// ============================================================
// Kernel 3: per (s',q) merge 256 chunk-lists -> global top-11
// one warp per (s',q); 8 warps per block
// ============================================================
__global__ __launch_bounds__(256) void reduce_kernel() {
    __shared__ float msc[8][32][12];
    __shared__ int   mix[8][32][12];
    int w = threadIdx.x >> 5, lane = threadIdx.x & 31;
    int pair = blockIdx.x * 8 + w;        // 0..4095
    int sp = pair >> 10, q = pair & 1023;
    size_t base = ((size_t)sp * Q_ + q) * (size_t)(NCH * NB);

    float bs[NB]; int bi[NB];
    #pragma unroll
    for (int r = 0; r < NB; r++) { bs[r] = NEG_INF; bi[r] = 0; }
    for (int k = lane; k < NCH * NB; k += 32) {
        float v = g_cand_sc[base + k];
        if (v > bs[NB - 1]) {
            float cv = v; int ci = g_cand_ix[base + k];
            #pragma unroll
            for (int r = 0; r < NB; r++) {
                if (cv > bs[r]) {
                    float t0 = bs[r]; int t1 = bi[r];
                    bs[r] = cv; bi[r] = ci; cv = t0; ci = t1;
                }
            }
        }
    }
    #pragma unroll
    for (int r = 0; r < NB; r++) { msc[w][lane][r] = bs[r]; mix[w][lane][r] = bi[r]; }
    msc[w][lane][11] = NEG_INF; mix[w][lane][11] = 0;
    __syncwarp();

    int h = 0;
    size_t ob = ((size_t)sp * Q_ + q) * NB;
    for (int r = 0; r < NB; r++) {
        float v = msc[w][lane][h];
        float bv = v; int bl = lane;
        #pragma unroll
        for (int off = 16; off > 0; off >>= 1) {
            float ov = __shfl_down_sync(0xffffffffu, bv, off);
            int   ol = __shfl_down_sync(0xffffffffu, bl, off);
            if (ov > bv) { bv = ov; bl = ol; }
        }
        bl = __shfl_sync(0xffffffffu, bl, 0);
        if (lane == bl) {
            g_best_sc[ob + r] = v;
            g_best_ix[ob + r] = mix[w][lane][h];
            h++;
        }
        __syncwarp();
    }
}

// ============================================================
// Kernel 4: per (s,b) merge 4 x 11 -> top-10; write output
// out[0 .. 10239]      = gid as float   (S,B,K)
// out[10240 .. 20479]  = scores         (S,B,K)
// ============================================================
__global__ void final_kernel(float* __restrict__ out) {
    int q = blockIdx.x * blockDim.x + threadIdx.x;
    if (q >= Q_) return;
    float bs[KOUT]; int bg[KOUT];
    #pragma unroll
    for (int r = 0; r < KOUT; r++) { bs[r] = NEG_INF; bg[r] = -1; }
    for (int sp = 0; sp < S_; sp++) {
        size_t base = ((size_t)sp * Q_ + q) * NB;
        for (int r = 0; r < NB; r++) {
            float v = g_best_sc[base + r];
            if (v > bs[KOUT - 1]) {
                int gid = g_best_ix[base + r] * S_ + sp;
                float cv = v; int ci = gid;
                #pragma unroll
                for (int k = 0; k < KOUT; k++) {
                    if (cv > bs[k]) {
                        float t0 = bs[k]; int t1 = bg[k];
                        bs[k] = cv; bg[k] = ci; cv = t0; ci = t1;
                    }
                }
            }
        }
    }
    #pragma unroll
    for (int k = 0; k < KOUT; k++) {
        out[q * KOUT + k]            = (float)bg[k];
        out[Q_ * KOUT + q * KOUT + k] = bs[k];
    }
}

// ============================================================
extern "C" void kernel_launch(void* const* d_in, const int* in_sizes, int n_in,
                              void* d_out, int out_size) {
    const int*   relation = (const int*)d_in[0];
    const int*   head     = (const int*)d_in[1];
    const float* ent      = (const float*)d_in[2];
    const float* rel      = (const float*)d_in[3];
    float* out = (float*)d_out;

    cudaFuncSetAttribute(score_kernel, cudaFuncAttributeMaxDynamicSharedMemorySize, SMEM_BYTES);

    qvec_kernel<<<Q_, D_>>>(relation, head, ent, rel);
    dim3 g2(NCH, S_);
    score_kernel<<<g2, 256, SMEM_BYTES>>>(ent);
    reduce_kernel<<<512, 256>>>();
    final_kernel<<<4, 256>>>(out);
}

// round 3
// speedup vs baseline: 1.9854x; 1.9854x over previous
#include <cuda_runtime.h>
#include <cuda_bf16.h>
#include <cstdint>

#define S_   4
#define B_   256
#define Q_   1024
#define P_   32768
#define D_   256
#define NB   11
#define KOUT 10
#define NEG_INF (-1e30f)

#define PT    256           // p per score tile
#define NPT   128           // P_/PT
#define QT    128           // q per score tile
#define NQT   8             // Q_/QT
#define TOPT  16            // candidates kept per (q, ptile)
#define MSEL  32            // candidates rescored per (s',q)

// ---------------- static device scratch ----------------
__device__ float          g_qvec [Q_ * D_];
__device__ __nv_bfloat16  g_qvecb[Q_ * D_];
__device__ __nv_bfloat16  g_entb [(size_t)S_ * P_ * D_];         // 64MB
__device__ float g_cand_sc[(size_t)S_ * Q_ * NPT * TOPT];        // 33MB
__device__ int   g_cand_ix[(size_t)S_ * Q_ * NPT * TOPT];        // 33MB
__device__ float g_best_sc[S_ * Q_ * NB];
__device__ int   g_best_ix[S_ * Q_ * NB];

__device__ __forceinline__ uint32_t smem_to_u32(const void* p) {
    uint32_t a;
    asm("{ .reg .u64 t; cvta.to.shared.u64 t, %1; cvt.u32.u64 %0, t; }" : "=r"(a) : "l"(p));
    return a;
}

// 16B-chunk XOR swizzle within a row of 32 chunks (512B): conflict-free ldmatrix
__device__ __forceinline__ uint32_t swz(int row, int chunk) {
    int c = (chunk & ~7) | ((chunk ^ row) & 7);
    return (uint32_t)(row * 512 + c * 16);
}

__device__ __forceinline__ void ldsm_x4(uint32_t* r, uint32_t addr) {
    asm volatile("ldmatrix.sync.aligned.m8n8.x4.shared.b16 {%0,%1,%2,%3}, [%4];"
                 : "=r"(r[0]), "=r"(r[1]), "=r"(r[2]), "=r"(r[3]) : "r"(addr));
}
__device__ __forceinline__ void ldsm_x2(uint32_t* r, uint32_t addr) {
    asm volatile("ldmatrix.sync.aligned.m8n8.x2.shared.b16 {%0,%1}, [%2];"
                 : "=r"(r[0]), "=r"(r[1]) : "r"(addr));
}
__device__ __forceinline__ void mma16816(float* d, const uint32_t* a, const uint32_t* b) {
    asm volatile(
        "mma.sync.aligned.m16n8k16.row.col.f32.bf16.bf16.f32 "
        "{%0,%1,%2,%3}, {%4,%5,%6,%7}, {%8,%9}, {%0,%1,%2,%3};"
        : "+f"(d[0]), "+f"(d[1]), "+f"(d[2]), "+f"(d[3])
        : "r"(a[0]), "r"(a[1]), "r"(a[2]), "r"(a[3]), "r"(b[0]), "r"(b[1]));
}

// ============================================================
// Kernel 0a: ent f32 -> bf16
// ============================================================
__global__ void conv_kernel(const float* __restrict__ ent) {
    size_t i = ((size_t)blockIdx.x * blockDim.x + threadIdx.x) * 4;
    float4 v = *(const float4*)(ent + i);
    *(__nv_bfloat162*)(g_entb + i)     = __floats2bfloat162_rn(v.x, v.y);
    *(__nv_bfloat162*)(g_entb + i + 2) = __floats2bfloat162_rn(v.z, v.w);
}

// ============================================================
// Kernel 0b: qvec f32 + bf16
// ============================================================
__global__ void qvec_kernel(const int* __restrict__ relation,
                            const int* __restrict__ head,
                            const float* __restrict__ ent,
                            const float* __restrict__ rel) {
    int q = blockIdx.x, d = threadIdx.x;
    int s = q >> 8;
    int hd = head[q], rr = relation[q];
    float v = ent[((size_t)s * P_ + hd) * D_ + d] * rel[(size_t)rr * D_ + d];
    g_qvec[q * D_ + d]  = v;
    g_qvecb[q * D_ + d] = __float2bfloat16_rn(v);
}

// ============================================================
// Kernel 1: HMMA bf16 score + per-(q,ptile) top-16
// grid (8, 128, 4), block 512
// smem: A swz 64KB @0, B swz 128KB @65536 ; epilogue reuse:
//   sS f32 [128][260] @0 (133120B), scr_sc @133120, scr_ix @165888
// ============================================================
#define SM_B_OFF   65536
#define SM_SS_STR  260
#define SM_SCR_SC  133120
#define SM_SCR_IX  165888
#define SM_TOTAL   198656

__global__ __launch_bounds__(512) void score_kernel() {
    extern __shared__ char sm[];
    const uint32_t sbase = smem_to_u32(sm);
    const int tid = threadIdx.x;
    const int wid = tid >> 5, lane = tid & 31;
    const int qtile = blockIdx.x, ptile = blockIdx.y, sp = blockIdx.z;

    // ---- stage A: 128 rows x 256 bf16 ----
    {
        const __nv_bfloat16* src = g_qvecb + (size_t)qtile * QT * D_;
        #pragma unroll
        for (int it = 0; it < 8; it++) {
            int i = tid + it * 512;                 // 4096 chunks
            int row = i >> 5, ch = i & 31;
            uint4 v = *(const uint4*)(src + (size_t)row * D_ + ch * 8);
            *(uint4*)(sm + swz(row, ch)) = v;
        }
    }
    // ---- stage B: 256 rows x 256 bf16 ----
    {
        const __nv_bfloat16* src = g_entb + ((size_t)sp * P_ + (size_t)ptile * PT) * D_;
        #pragma unroll
        for (int it = 0; it < 16; it++) {
            int i = tid + it * 512;                 // 8192 chunks
            int row = i >> 5, ch = i & 31;
            uint4 v = *(const uint4*)(src + (size_t)row * D_ + ch * 8);
            *(uint4*)(sm + SM_B_OFF + swz(row, ch)) = v;
        }
    }
    __syncthreads();

    // ---- MMA main loop: warp tile 64q x 32p ----
    const int wq = wid >> 3;          // 0..1
    const int wp = wid & 7;           // 0..7
    const int q0 = wq * 64, p0 = wp * 32;

    float acc[4][4][4];
    #pragma unroll
    for (int mi = 0; mi < 4; mi++)
        #pragma unroll
        for (int ni = 0; ni < 4; ni++)
            #pragma unroll
            for (int f = 0; f < 4; f++) acc[mi][ni][f] = 0.f;

    const int arow = (lane & 15);
    const int asel = (lane >> 4);       // +chunk for A ldmatrix
    const int brow = (lane & 7);
    const int bsel = ((lane >> 3) & 1); // +chunk for B ldmatrix (lanes 0-15 meaningful)

    #pragma unroll
    for (int ks = 0; ks < 16; ks++) {   // K = 256 = 16 x k16
        const int ch0 = ks * 2;
        uint32_t a[4][4], b[4][2];
        #pragma unroll
        for (int mi = 0; mi < 4; mi++) {
            int r = q0 + mi * 16 + arow;
            ldsm_x4(a[mi], sbase + swz(r, ch0 + asel));
        }
        #pragma unroll
        for (int ni = 0; ni < 4; ni++) {
            int r = p0 + ni * 8 + brow;
            ldsm_x2(b[ni], sbase + SM_B_OFF + swz(r, ch0 + bsel));
        }
        #pragma unroll
        for (int mi = 0; mi < 4; mi++)
            #pragma unroll
            for (int ni = 0; ni < 4; ni++)
                mma16816(acc[mi][ni], a[mi], b[ni]);
    }
    __syncthreads();   // everyone done reading staged tiles

    // ---- scores -> smem [128][260] ----
    float* sS = (float*)sm;
    {
        int rr = lane >> 2, cc = 2 * (lane & 3);
        #pragma unroll
        for (int mi = 0; mi < 4; mi++)
            #pragma unroll
            for (int ni = 0; ni < 4; ni++) {
                int r = q0 + mi * 16 + rr;
                int c = p0 + ni * 8 + cc;
                sS[r * SM_SS_STR + c]                    = acc[mi][ni][0];
                sS[r * SM_SS_STR + c + 1]                = acc[mi][ni][1];
                sS[(r + 8) * SM_SS_STR + c]              = acc[mi][ni][2];
                sS[(r + 8) * SM_SS_STR + c + 1]          = acc[mi][ni][3];
            }
    }
    __syncthreads();

    // ---- per-thread top-16 over 64 interleaved p's ----
    float* scr_sc = (float*)(sm + SM_SCR_SC);
    int*   scr_ix = (int*)(sm + SM_SCR_IX);
    const int tq = tid >> 2, tsg = tid & 3;
    const int pg0 = ptile * PT;
    {
        float bs[TOPT]; int bi[TOPT];
        #pragma unroll
        for (int r = 0; r < TOPT; r++) { bs[r] = NEG_INF; bi[r] = 0; }
        for (int i = 0; i < 64; i++) {
            int p = tsg + (i << 2);
            float v = sS[tq * SM_SS_STR + p];
            if (v > bs[TOPT - 1]) {
                float cv = v; int ci = pg0 + p;
                #pragma unroll
                for (int r = 0; r < TOPT; r++) {
                    if (cv > bs[r]) {
                        float t0 = bs[r]; int t1 = bi[r];
                        bs[r] = cv; bi[r] = ci; cv = t0; ci = t1;
                    }
                }
            }
        }
        #pragma unroll
        for (int r = 0; r < TOPT; r++) {
            scr_sc[(tq * 4 + tsg) * TOPT + r] = bs[r];
            scr_ix[(tq * 4 + tsg) * TOPT + r] = bi[r];
        }
    }
    __syncthreads();

    // ---- leader: merge 4 sorted lists -> sorted top-16, write gmem ----
    if (tsg == 0) {
        int q = qtile * QT + tq;
        size_t ob = (((size_t)sp * Q_ + q) * NPT + ptile) * TOPT;
        int h0 = 0, h1 = 0, h2 = 0, h3 = 0;
        const float* L = scr_sc + (size_t)tq * 4 * TOPT;
        const int*   X = scr_ix + (size_t)tq * 4 * TOPT;
        #pragma unroll
        for (int r = 0; r < TOPT; r++) {
            float best = NEG_INF; int bj = 0, bh = 0;
            #define TRYM(j, h) { float v = ((h) < TOPT) ? L[(j) * TOPT + (h)] : NEG_INF; \
                                 if (v > best) { best = v; bj = (j); bh = (h); } }
            TRYM(0, h0) TRYM(1, h1) TRYM(2, h2) TRYM(3, h3)
            #undef TRYM
            g_cand_sc[ob + r] = best;
            g_cand_ix[ob + r] = X[bj * TOPT + bh];
            if      (bj == 0) h0++;
            else if (bj == 1) h1++;
            else if (bj == 2) h2++;
            else              h3++;
        }
    }
}

// ============================================================
// Kernel 2: per (s',q): merge 128 sorted top-16 lists -> approx
// top-32, rescore exactly in f32, exact top-11.
// ============================================================
__global__ __launch_bounds__(128) void select_kernel(const float* __restrict__ ent) {
    __shared__ float cs[NPT * TOPT];
    __shared__ int   ci[NPT * TOPT];
    __shared__ int   sel_ix[MSEL];
    __shared__ float partial[MSEL][4];
    __shared__ float fsc[MSEL];

    const int tid = threadIdx.x;
    const int pair = blockIdx.x;
    const int sp = pair >> 10, q = pair & 1023;
    size_t base = ((size_t)sp * Q_ + q) * (size_t)(NPT * TOPT);

    for (int i = tid; i < NPT * TOPT; i += 128) {
        cs[i] = g_cand_sc[base + i];
        ci[i] = g_cand_ix[base + i];
    }
    __syncthreads();

    if (tid < 32) {
        int h0 = 0, h1 = 0, h2 = 0, h3 = 0;
        for (int r = 0; r < MSEL; r++) {
            float best = NEG_INF; int bj = 0;
            #define TRYL(j, h) { float v = ((h) < TOPT) ? cs[(tid * 4 + (j)) * TOPT + (h)] : NEG_INF; \
                                 if (v > best) { best = v; bj = (j); } }
            TRYL(0, h0) TRYL(1, h1) TRYL(2, h2) TRYL(3, h3)
            #undef TRYL
            float bv = best; int bl = tid;
            #pragma unroll
            for (int off = 16; off > 0; off >>= 1) {
                float ov = __shfl_down_sync(0xffffffffu, bv, off);
                int   ol = __shfl_down_sync(0xffffffffu, bl, off);
                if (ov > bv) { bv = ov; bl = ol; }
            }
            bl = __shfl_sync(0xffffffffu, bl, 0);
            if (tid == bl) {
                int h = (bj == 0) ? h0 : (bj == 1) ? h1 : (bj == 2) ? h2 : h3;
                sel_ix[r] = ci[(tid * 4 + bj) * TOPT + h];
                if      (bj == 0) h0++;
                else if (bj == 1) h1++;
                else if (bj == 2) h2++;
                else              h3++;
            }
            __syncwarp();
        }
    }
    __syncthreads();

    {
        int c = tid >> 2, part = tid & 3;
        int p = sel_ix[c];
        const float4* qv = (const float4*)(g_qvec + (size_t)q * D_ + part * 64);
        const float4* ev = (const float4*)(ent + ((size_t)sp * P_ + p) * D_ + part * 64);
        float accv = 0.f;
        #pragma unroll
        for (int i = 0; i < 16; i++) {
            float4 a = qv[i], e = ev[i];
            accv = fmaf(a.x, e.x, fmaf(a.y, e.y, fmaf(a.z, e.z, fmaf(a.w, e.w, accv))));
        }
        partial[c][part] = accv;
    }
    __syncthreads();
    if (tid < MSEL) fsc[tid] = partial[tid][0] + partial[tid][1] + partial[tid][2] + partial[tid][3];
    __syncthreads();

    if (tid < 32) {
        float v = fsc[tid];
        int ix = sel_ix[tid];
        size_t ob = ((size_t)sp * Q_ + q) * NB;
        for (int r = 0; r < NB; r++) {
            float bv = v; int bl = tid;
            #pragma unroll
            for (int off = 16; off > 0; off >>= 1) {
                float ov = __shfl_down_sync(0xffffffffu, bv, off);
                int   ol = __shfl_down_sync(0xffffffffu, bl, off);
                if (ov > bv) { bv = ov; bl = ol; }
            }
            bl = __shfl_sync(0xffffffffu, bl, 0);
            float wv = __shfl_sync(0xffffffffu, v, bl);
            int   wi = __shfl_sync(0xffffffffu, ix, bl);
            if (tid == 0) { g_best_sc[ob + r] = wv; g_best_ix[ob + r] = wi; }
            if (tid == bl) v = NEG_INF;
            __syncwarp();
        }
    }
}

// ============================================================
// Kernel 3: per (s,b) merge 4 x 11 -> top-10; write output
// ============================================================
__global__ void final_kernel(float* __restrict__ out) {
    int q = blockIdx.x * blockDim.x + threadIdx.x;
    if (q >= Q_) return;
    float bs[KOUT]; int bg[KOUT];
    #pragma unroll
    for (int r = 0; r < KOUT; r++) { bs[r] = NEG_INF; bg[r] = -1; }
    for (int sp = 0; sp < S_; sp++) {
        size_t base = ((size_t)sp * Q_ + q) * NB;
        for (int r = 0; r < NB; r++) {
            float v = g_best_sc[base + r];
            if (v > bs[KOUT - 1]) {
                int gid = g_best_ix[base + r] * S_ + sp;
                float cv = v; int ci = gid;
                #pragma unroll
                for (int k = 0; k < KOUT; k++) {
                    if (cv > bs[k]) {
                        float t0 = bs[k]; int t1 = bg[k];
                        bs[k] = cv; bg[k] = ci; cv = t0; ci = t1;
                    }
                }
            }
        }
    }
    #pragma unroll
    for (int k = 0; k < KOUT; k++) {
        out[q * KOUT + k]             = (float)bg[k];
        out[Q_ * KOUT + q * KOUT + k] = bs[k];
    }
}

// ============================================================
extern "C" void kernel_launch(void* const* d_in, const int* in_sizes, int n_in,
                              void* d_out, int out_size) {
    const int*   relation = (const int*)d_in[0];
    const int*   head     = (const int*)d_in[1];
    const float* ent      = (const float*)d_in[2];
    const float* rel      = (const float*)d_in[3];
    float* out = (float*)d_out;

    cudaFuncSetAttribute(score_kernel, cudaFuncAttributeMaxDynamicSharedMemorySize, SM_TOTAL);

    conv_kernel<<<(int)(((size_t)S_ * P_ * D_ / 4) / 256), 256>>>(ent);
    qvec_kernel<<<Q_, D_>>>(relation, head, ent, rel);
    dim3 g1(NQT, NPT, S_);
    score_kernel<<<g1, 512, SM_TOTAL>>>();
    select_kernel<<<S_ * Q_, 128>>>(ent);
    final_kernel<<<4, 256>>>(out);
}

// round 4
// speedup vs baseline: 4.8173x; 2.4264x over previous
#include <cuda_runtime.h>
#include <cuda_fp16.h>
#include <cstdint>

#define S_   4
#define B_   256
#define Q_   1024
#define P_   32768
#define D_   256
#define NB   11
#define KOUT 10
#define NEG_INF (-1e30f)

#define PT    256           // p per score tile
#define NPT   128           // P_/PT
#define QT    128           // q per score tile
#define NQT   8             // Q_/QT
#define TOPT  8             // candidates kept per (q, ptile)
#define MSEL  64            // candidates rescored per (s',q)

// ---------------- static device scratch ----------------
__device__ float  g_qvec [Q_ * D_];
__device__ __half g_qvech[Q_ * D_];
__device__ __half g_enth [(size_t)S_ * P_ * D_];                 // 64MB
__device__ float  g_cand_sc[(size_t)S_ * Q_ * NPT * TOPT];       // 16MB
__device__ int    g_cand_ix[(size_t)S_ * Q_ * NPT * TOPT];       // 16MB
__device__ float  g_best_sc[S_ * Q_ * NB];
__device__ int    g_best_ix[S_ * Q_ * NB];

__device__ __forceinline__ uint32_t smem_to_u32(const void* p) {
    uint32_t a;
    asm("{ .reg .u64 t; cvta.to.shared.u64 t, %1; cvt.u32.u64 %0, t; }" : "=r"(a) : "l"(p));
    return a;
}
// 16B-chunk XOR swizzle within a 512B row (32 chunks): conflict-free ldmatrix
__device__ __forceinline__ uint32_t swz(int row, int chunk) {
    int c = (chunk & ~7) | ((chunk ^ row) & 7);
    return (uint32_t)(row * 512 + c * 16);
}
__device__ __forceinline__ void cp_async16(uint32_t smem, const void* gmem) {
    asm volatile("cp.async.cg.shared.global [%0], [%1], 16;" :: "r"(smem), "l"(gmem));
}
__device__ __forceinline__ void cp_commit_wait() {
    asm volatile("cp.async.commit_group;");
    asm volatile("cp.async.wait_group 0;");
}
__device__ __forceinline__ void ldsm_x4(uint32_t* r, uint32_t addr) {
    asm volatile("ldmatrix.sync.aligned.m8n8.x4.shared.b16 {%0,%1,%2,%3}, [%4];"
                 : "=r"(r[0]), "=r"(r[1]), "=r"(r[2]), "=r"(r[3]) : "r"(addr));
}
__device__ __forceinline__ void ldsm_x2(uint32_t* r, uint32_t addr) {
    asm volatile("ldmatrix.sync.aligned.m8n8.x2.shared.b16 {%0,%1}, [%2];"
                 : "=r"(r[0]), "=r"(r[1]) : "r"(addr));
}
// f16 inputs, f16 accumulation (D=C=f16x2 pair)
__device__ __forceinline__ void mma16816_f16(uint32_t* d, const uint32_t* a, const uint32_t* b) {
    asm volatile(
        "mma.sync.aligned.m16n8k16.row.col.f16.f16.f16.f16 "
        "{%0,%1}, {%2,%3,%4,%5}, {%6,%7}, {%0,%1};"
        : "+r"(d[0]), "+r"(d[1])
        : "r"(a[0]), "r"(a[1]), "r"(a[2]), "r"(a[3]), "r"(b[0]), "r"(b[1]));
}

// ============================================================
// Kernel 0a: ent f32 -> f16
// ============================================================
__global__ void conv_kernel(const float* __restrict__ ent) {
    size_t i = ((size_t)blockIdx.x * blockDim.x + threadIdx.x) * 4;
    float4 v = *(const float4*)(ent + i);
    __half2 lo = __floats2half2_rn(v.x, v.y);
    __half2 hi = __floats2half2_rn(v.z, v.w);
    *(__half2*)(g_enth + i)     = lo;
    *(__half2*)(g_enth + i + 2) = hi;
}

// ============================================================
// Kernel 0b: qvec f32 + f16
// ============================================================
__global__ void qvec_kernel(const int* __restrict__ relation,
                            const int* __restrict__ head,
                            const float* __restrict__ ent,
                            const float* __restrict__ rel) {
    int q = blockIdx.x, d = threadIdx.x;
    int s = q >> 8;
    int hd = head[q], rr = relation[q];
    float v = ent[((size_t)s * P_ + hd) * D_ + d] * rel[(size_t)rr * D_ + d];
    g_qvec[q * D_ + d]  = v;
    g_qvech[q * D_ + d] = __float2half_rn(v);
}

// ============================================================
// Kernel 1: HMMA f16 score + per-(q,ptile) top-8
// grid (8, 128, 4), block 512
// ============================================================
#define SM_B_OFF   65536
#define SM_SS_STR  260
#define SM_SCR_SC  133120
#define SM_SCR_IX  149504
#define SM_TOTAL   196608

__global__ __launch_bounds__(512) void score_kernel() {
    extern __shared__ char sm[];
    const uint32_t sbase = smem_to_u32(sm);
    const int tid = threadIdx.x;
    const int wid = tid >> 5, lane = tid & 31;
    const int qtile = blockIdx.x, ptile = blockIdx.y, sp = blockIdx.z;

    // ---- stage A: 128 rows x 256 f16 via cp.async ----
    {
        const __half* src = g_qvech + (size_t)qtile * QT * D_;
        #pragma unroll
        for (int it = 0; it < 8; it++) {
            int i = tid + it * 512;
            int row = i >> 5, ch = i & 31;
            cp_async16(sbase + swz(row, ch), src + (size_t)row * D_ + ch * 8);
        }
    }
    // ---- stage B: 256 rows x 256 f16 via cp.async ----
    {
        const __half* src = g_enth + ((size_t)sp * P_ + (size_t)ptile * PT) * D_;
        #pragma unroll
        for (int it = 0; it < 16; it++) {
            int i = tid + it * 512;
            int row = i >> 5, ch = i & 31;
            cp_async16(sbase + SM_B_OFF + swz(row, ch), src + (size_t)row * D_ + ch * 8);
        }
    }
    cp_commit_wait();
    __syncthreads();

    // ---- MMA main loop: warp tile 64q x 32p, f16 accum ----
    const int wq = wid >> 3;
    const int wp = wid & 7;
    const int q0 = wq * 64, p0 = wp * 32;

    uint32_t d[4][4][2];
    #pragma unroll
    for (int mi = 0; mi < 4; mi++)
        #pragma unroll
        for (int ni = 0; ni < 4; ni++) { d[mi][ni][0] = 0u; d[mi][ni][1] = 0u; }

    const int arow = (lane & 15);
    const int asel = (lane >> 4);
    const int brow = (lane & 7);
    const int bsel = ((lane >> 3) & 1);

    #pragma unroll
    for (int ks = 0; ks < 16; ks++) {
        const int ch0 = ks * 2;
        uint32_t a[4][4], b[4][2];
        #pragma unroll
        for (int mi = 0; mi < 4; mi++)
            ldsm_x4(a[mi], sbase + swz(q0 + mi * 16 + arow, ch0 + asel));
        #pragma unroll
        for (int ni = 0; ni < 4; ni++)
            ldsm_x2(b[ni], sbase + SM_B_OFF + swz(p0 + ni * 8 + brow, ch0 + bsel));
        #pragma unroll
        for (int mi = 0; mi < 4; mi++)
            #pragma unroll
            for (int ni = 0; ni < 4; ni++)
                mma16816_f16(d[mi][ni], a[mi], b[ni]);
    }
    __syncthreads();

    // ---- promote f16 accum -> f32 scores in smem [128][260] ----
    float* sS = (float*)sm;
    {
        int rr = lane >> 2, cc = 2 * (lane & 3);
        #pragma unroll
        for (int mi = 0; mi < 4; mi++)
            #pragma unroll
            for (int ni = 0; ni < 4; ni++) {
                int r = q0 + mi * 16 + rr;
                int c = p0 + ni * 8 + cc;
                float2 lo = __half22float2(*(__half2*)&d[mi][ni][0]);
                float2 hi = __half22float2(*(__half2*)&d[mi][ni][1]);
                sS[r * SM_SS_STR + c]           = lo.x;
                sS[r * SM_SS_STR + c + 1]       = lo.y;
                sS[(r + 8) * SM_SS_STR + c]     = hi.x;
                sS[(r + 8) * SM_SS_STR + c + 1] = hi.y;
            }
    }
    __syncthreads();

    // ---- per-thread top-8 over 64 interleaved p's ----
    float* scr_sc = (float*)(sm + SM_SCR_SC);
    int*   scr_ix = (int*)(sm + SM_SCR_IX);
    const int tq = tid >> 2, tsg = tid & 3;
    const int pg0 = ptile * PT;
    {
        float bs[TOPT]; int bi[TOPT];
        #pragma unroll
        for (int r = 0; r < TOPT; r++) { bs[r] = NEG_INF; bi[r] = 0; }
        for (int i = 0; i < 64; i++) {
            int p = tsg + (i << 2);
            float v = sS[tq * SM_SS_STR + p];
            if (v > bs[TOPT - 1]) {
                float cv = v; int ci = pg0 + p;
                #pragma unroll
                for (int r = 0; r < TOPT; r++) {
                    if (cv > bs[r]) {
                        float t0 = bs[r]; int t1 = bi[r];
                        bs[r] = cv; bi[r] = ci; cv = t0; ci = t1;
                    }
                }
            }
        }
        #pragma unroll
        for (int r = 0; r < TOPT; r++) {
            scr_sc[(tq * 4 + tsg) * TOPT + r] = bs[r];
            scr_ix[(tq * 4 + tsg) * TOPT + r] = bi[r];
        }
    }
    __syncthreads();

    // ---- leader: merge 4 sorted top-8 lists -> sorted top-8, write ----
    if (tsg == 0) {
        int q = qtile * QT + tq;
        size_t ob = (((size_t)sp * Q_ + q) * NPT + ptile) * TOPT;
        int h0 = 0, h1 = 0, h2 = 0, h3 = 0;
        const float* L = scr_sc + (size_t)tq * 4 * TOPT;
        const int*   X = scr_ix + (size_t)tq * 4 * TOPT;
        #pragma unroll
        for (int r = 0; r < TOPT; r++) {
            float best = NEG_INF; int bj = 0, bh = 0;
            #define TRYM(j, h) { float v = ((h) < TOPT) ? L[(j) * TOPT + (h)] : NEG_INF; \
                                 if (v > best) { best = v; bj = (j); bh = (h); } }
            TRYM(0, h0) TRYM(1, h1) TRYM(2, h2) TRYM(3, h3)
            #undef TRYM
            g_cand_sc[ob + r] = best;
            g_cand_ix[ob + r] = X[bj * TOPT + bh];
            if      (bj == 0) h0++;
            else if (bj == 1) h1++;
            else if (bj == 2) h2++;
            else              h3++;
        }
    }
}

// ============================================================
// Kernel 2: per (s',q): tournament over 128 sorted top-8 lists
// -> approx top-64, exact f32 rescore, exact top-11.
// grid 4096, block 256
// ============================================================
__global__ __launch_bounds__(256) void select_kernel(const float* __restrict__ ent) {
    __shared__ float cs_t[TOPT][NPT];      // [rank][list]
    __shared__ int   ci_t[TOPT][NPT];
    __shared__ int   sel_ix[MSEL];
    __shared__ float partial[MSEL][4];
    __shared__ float fsc[MSEL];

    const int tid = threadIdx.x;
    const int pair = blockIdx.x;
    const int sp = pair >> 10, q = pair & 1023;
    size_t base = ((size_t)sp * Q_ + q) * (size_t)(NPT * TOPT);

    // load transposed: elem e -> cs_t[e & 7][e >> 3]
    for (int e = tid; e < NPT * TOPT; e += 256) {
        cs_t[e & 7][e >> 3] = g_cand_sc[base + e];
        ci_t[e & 7][e >> 3] = g_cand_ix[base + e];
    }
    __syncthreads();

    // warp 0: tournament; lane owns 4 lists with register heads
    if (tid < 32) {
        int   h[4];
        float hv[4];
        #pragma unroll
        for (int j = 0; j < 4; j++) { h[j] = 0; hv[j] = cs_t[0][tid * 4 + j]; }
        for (int r = 0; r < MSEL; r++) {
            float best = hv[0]; int bj = 0;
            #pragma unroll
            for (int j = 1; j < 4; j++) if (hv[j] > best) { best = hv[j]; bj = j; }
            float bv = best; int bl = tid;
            #pragma unroll
            for (int off = 16; off > 0; off >>= 1) {
                float ov = __shfl_down_sync(0xffffffffu, bv, off);
                int   ol = __shfl_down_sync(0xffffffffu, bl, off);
                if (ov > bv) { bv = ov; bl = ol; }
            }
            bl = __shfl_sync(0xffffffffu, bl, 0);
            if (tid == bl) {
                int list = tid * 4 + bj;
                sel_ix[r] = ci_t[h[bj]][list];
                h[bj]++;
                hv[bj] = (h[bj] < TOPT) ? cs_t[h[bj]][list] : NEG_INF;
            }
            __syncwarp();
        }
    }
    __syncthreads();

    // exact f32 rescore: 4 threads per candidate, 64 candidates
    {
        int c = tid >> 2, part = tid & 3;
        int p = sel_ix[c];
        const float4* qv = (const float4*)(g_qvec + (size_t)q * D_ + part * 64);
        const float4* ev = (const float4*)(ent + ((size_t)sp * P_ + p) * D_ + part * 64);
        float accv = 0.f;
        #pragma unroll
        for (int i = 0; i < 16; i++) {
            float4 a = qv[i], e = ev[i];
            accv = fmaf(a.x, e.x, fmaf(a.y, e.y, fmaf(a.z, e.z, fmaf(a.w, e.w, accv))));
        }
        partial[c][part] = accv;
    }
    __syncthreads();
    if (tid < MSEL) fsc[tid] = partial[tid][0] + partial[tid][1] + partial[tid][2] + partial[tid][3];
    __syncthreads();

    // warp 0: exact top-11 of 64 (2 values per lane in registers)
    if (tid < 32) {
        float v0 = fsc[tid], v1 = fsc[tid + 32];
        int   x0 = sel_ix[tid], x1 = sel_ix[tid + 32];
        size_t ob = ((size_t)sp * Q_ + q) * NB;
        for (int r = 0; r < NB; r++) {
            float lv = v0; int lsel = 0;
            if (v1 > lv) { lv = v1; lsel = 1; }
            float bv = lv; int bl = tid;
            #pragma unroll
            for (int off = 16; off > 0; off >>= 1) {
                float ov = __shfl_down_sync(0xffffffffu, bv, off);
                int   ol = __shfl_down_sync(0xffffffffu, bl, off);
                if (ov > bv) { bv = ov; bl = ol; }
            }
            bl = __shfl_sync(0xffffffffu, bl, 0);
            int lx = lsel ? x1 : x0;
            float wv = __shfl_sync(0xffffffffu, lv, bl);
            int   wx = __shfl_sync(0xffffffffu, lx, bl);
            if (tid == 0) { g_best_sc[ob + r] = wv; g_best_ix[ob + r] = wx; }
            if (tid == bl) { if (lsel) v1 = NEG_INF; else v0 = NEG_INF; }
            __syncwarp();
        }
    }
}

// ============================================================
// Kernel 3: per (s,b) merge 4 x 11 -> top-10; write output
// ============================================================
__global__ void final_kernel(float* __restrict__ out) {
    int q = blockIdx.x * blockDim.x + threadIdx.x;
    if (q >= Q_) return;
    float bs[KOUT]; int bg[KOUT];
    #pragma unroll
    for (int r = 0; r < KOUT; r++) { bs[r] = NEG_INF; bg[r] = -1; }
    for (int sp = 0; sp < S_; sp++) {
        size_t base = ((size_t)sp * Q_ + q) * NB;
        for (int r = 0; r < NB; r++) {
            float v = g_best_sc[base + r];
            if (v > bs[KOUT - 1]) {
                int gid = g_best_ix[base + r] * S_ + sp;
                float cv = v; int ci = gid;
                #pragma unroll
                for (int k = 0; k < KOUT; k++) {
                    if (cv > bs[k]) {
                        float t0 = bs[k]; int t1 = bg[k];
                        bs[k] = cv; bg[k] = ci; cv = t0; ci = t1;
                    }
                }
            }
        }
    }
    #pragma unroll
    for (int k = 0; k < KOUT; k++) {
        out[q * KOUT + k]             = (float)bg[k];
        out[Q_ * KOUT + q * KOUT + k] = bs[k];
    }
}

// ============================================================
extern "C" void kernel_launch(void* const* d_in, const int* in_sizes, int n_in,
                              void* d_out, int out_size) {
    const int*   relation = (const int*)d_in[0];
    const int*   head     = (const int*)d_in[1];
    const float* ent      = (const float*)d_in[2];
    const float* rel      = (const float*)d_in[3];
    float* out = (float*)d_out;

    cudaFuncSetAttribute(score_kernel, cudaFuncAttributeMaxDynamicSharedMemorySize, SM_TOTAL);

    conv_kernel<<<(int)(((size_t)S_ * P_ * D_ / 4) / 256), 256>>>(ent);
    qvec_kernel<<<Q_, D_>>>(relation, head, ent, rel);
    dim3 g1(NQT, NPT, S_);
    score_kernel<<<g1, 512, SM_TOTAL>>>();
    select_kernel<<<S_ * Q_, 256>>>(ent);
    final_kernel<<<4, 256>>>(out);
}